// round 5
// baseline (speedup 1.0000x reference)
#include <cuda_runtime.h>
#include <cuda_bf16.h>

// Problem constants
#define BATCH   4
#define TLEN    1024
#define PIX     1296          // 27*48
#define NBINS   512
#define LOOKUP  101
#define PAD     50
#define OUTDIM  128
#define NFRAMES (BATCH * TLEN)    // 4096

// Band kernel tiling
#define TT      8                  // t-rows per CTA
#define RR      (TT + 2 * PAD)     // 108 staged rows
#define BAND_SMEM (RR * NBINS * 4) // 221184 bytes

// GEMV tiling
#define GT      16                 // (b,t) rows per CTA
#define GEMV_SMEM ((LOOKUP * OUTDIM + GT * LOOKUP) * 4) // 58176 bytes

// Scratch (static device globals: no allocation allowed)
__device__ float g_hist[NFRAMES * NBINS];   // 8 MB, L2-normalized histograms
__device__ float g_win[NFRAMES * LOOKUP];   // 1.65 MB, banded similarities

// ---------------------------------------------------------------------------
// Kernel 1: per-frame 512-bin color histogram + L2 normalize.
// One CTA per frame. HBM-bound on the 64MB int32 input.
// ---------------------------------------------------------------------------
__global__ void __launch_bounds__(256) hist_kernel(const int* __restrict__ frames) {
    __shared__ int h[NBINS];
    __shared__ float red[9];

    const int f = blockIdx.x;
    const int tid = threadIdx.x;

    for (int i = tid; i < NBINS; i += 256) h[i] = 0;
    __syncthreads();

    const int* fp = frames + (long long)f * (PIX * 3);
    for (int p = tid; p < PIX; p += 256) {
        int r = fp[3 * p + 0];
        int g = fp[3 * p + 1];
        int b = fp[3 * p + 2];
        int bin = ((r >> 5) << 6) | ((g >> 5) << 3) | (b >> 5);
        atomicAdd(&h[bin], 1);
    }
    __syncthreads();

    // sum of squares -> 1/norm
    float s = 0.0f;
    for (int i = tid; i < NBINS; i += 256) {
        float v = (float)h[i];
        s = fmaf(v, v, s);
    }
    #pragma unroll
    for (int off = 16; off; off >>= 1) s += __shfl_xor_sync(0xffffffffu, s, off);
    if ((tid & 31) == 0) red[tid >> 5] = s;
    __syncthreads();
    if (tid == 0) {
        float tot = 0.0f;
        #pragma unroll
        for (int i = 0; i < 8; i++) tot += red[i];
        red[8] = 1.0f / sqrtf(fmaxf(tot, 1e-24f));
    }
    __syncthreads();
    const float inv = red[8];

    float* dst = g_hist + (long long)f * NBINS;
    for (int i = tid; i < NBINS; i += 256)
        dst[i] = (float)h[i] * inv;
}

// ---------------------------------------------------------------------------
// Kernel 2: banded similarities.
//   win[b, t, l] = dot(x[b,t], x[b, t+l-50]) over 512 dims (0 if out of range)
// CTA handles TT=8 consecutive t of one batch. Stages the 108 needed rows in
// SMEM (216KB), keeps the 8 query rows in registers (128 regs/thread), so each
// staged row chunk is LDS-read once per warp and FMA'd against 8 queries.
// ---------------------------------------------------------------------------
__device__ __forceinline__ float dot4(float4 a, float4 b, float s) {
    s = fmaf(a.x, b.x, s);
    s = fmaf(a.y, b.y, s);
    s = fmaf(a.z, b.z, s);
    s = fmaf(a.w, b.w, s);
    return s;
}

__global__ void __launch_bounds__(256, 1) band_kernel() {
    extern __shared__ float rows[];            // RR * NBINS floats
    float4* rows4 = reinterpret_cast<float4*>(rows);

    const int t0  = blockIdx.x * TT;
    const int b   = blockIdx.y;
    const int tid = threadIdx.x;

    // Stage rows [t0-50, t0+57] (zero-fill out-of-range) into SMEM.
    const float4* gh4 = reinterpret_cast<const float4*>(g_hist);
    for (int idx = tid; idx < RR * (NBINS / 4); idx += 256) {
        int r = idx >> 7;          // NBINS/4 = 128 float4 per row
        int c = idx & 127;
        int j = t0 - PAD + r;
        float4 v = make_float4(0.f, 0.f, 0.f, 0.f);
        if (j >= 0 && j < TLEN)
            v = gh4[(b * TLEN + j) * (NBINS / 4) + c];
        rows4[idx] = v;
    }
    __syncthreads();

    const int w    = tid >> 5;
    const int lane = tid & 31;

    // Query rows (t0..t0+7) in registers: each lane owns k-chunks
    // {lane, lane+32, lane+64, lane+96} (float4 granularity).
    float4 xa[TT][4];
    #pragma unroll
    for (int ti = 0; ti < TT; ti++) {
        #pragma unroll
        for (int i = 0; i < 4; i++)
            xa[ti][i] = rows4[(PAD + ti) * 128 + lane + 32 * i];
    }

    // Each warp sweeps its subset of staged rows r (= key row j = t0-50+r).
    for (int r = w; r < RR; r += 8) {
        float4 xb0 = rows4[r * 128 + lane];
        float4 xb1 = rows4[r * 128 + lane + 32];
        float4 xb2 = rows4[r * 128 + lane + 64];
        float4 xb3 = rows4[r * 128 + lane + 96];

        float acc[TT];
        #pragma unroll
        for (int ti = 0; ti < TT; ti++) {
            float s = 0.0f;
            s = dot4(xa[ti][0], xb0, s);
            s = dot4(xa[ti][1], xb1, s);
            s = dot4(xa[ti][2], xb2, s);
            s = dot4(xa[ti][3], xb3, s);
            acc[ti] = s;
        }

        #pragma unroll
        for (int ti = 0; ti < TT; ti++) {
            float v = acc[ti];
            #pragma unroll
            for (int off = 16; off; off >>= 1)
                v += __shfl_xor_sync(0xffffffffu, v, off);
            int l = r - ti;                      // l = j - t + 50
            if (lane == ti && l >= 0 && l < LOOKUP)
                g_win[(b * TLEN + t0 + ti) * LOOKUP + l] = v;
        }
    }
}

// ---------------------------------------------------------------------------
// Kernel 3: out[bt, o] = relu( sum_l win[bt, l] * W[l, o] + bias[o] )
// CTA handles GT=16 (b,t) rows; fc_w staged in SMEM once per CTA.
// ---------------------------------------------------------------------------
__global__ void __launch_bounds__(256) gemv_kernel(const float* __restrict__ W,
                                                   const float* __restrict__ bias,
                                                   float* __restrict__ out) {
    extern __shared__ float sm[];
    float* Wsh   = sm;                       // LOOKUP*OUTDIM
    float* winsh = sm + LOOKUP * OUTDIM;     // GT*LOOKUP

    const int tid = threadIdx.x;
    const int f0  = blockIdx.x * GT;

    const float4* W4   = reinterpret_cast<const float4*>(W);
    float4*       Wsh4 = reinterpret_cast<float4*>(Wsh);
    for (int i = tid; i < LOOKUP * (OUTDIM / 4); i += 256) Wsh4[i] = W4[i];
    for (int i = tid; i < GT * LOOKUP; i += 256) winsh[i] = g_win[f0 * LOOKUP + i];
    __syncthreads();

    const int o    = tid & 127;
    const int half = tid >> 7;               // 0 or 1

    float acc[GT / 2];
    const float bo = bias[o];
    #pragma unroll
    for (int i = 0; i < GT / 2; i++) acc[i] = bo;

    for (int l = 0; l < LOOKUP; l++) {
        float wv = Wsh[l * OUTDIM + o];
        #pragma unroll
        for (int i = 0; i < GT / 2; i++)
            acc[i] = fmaf(winsh[(half + 2 * i) * LOOKUP + l], wv, acc[i]);
    }

    #pragma unroll
    for (int i = 0; i < GT / 2; i++)
        out[(f0 + half + 2 * i) * OUTDIM + o] = fmaxf(acc[i], 0.0f);
}

// ---------------------------------------------------------------------------
extern "C" void kernel_launch(void* const* d_in, const int* in_sizes, int n_in,
                              void* d_out, int out_size) {
    const int*   frames = (const int*)d_in[0];
    const float* fc_w   = (const float*)d_in[1];
    const float* fc_b   = (const float*)d_in[2];
    float*       out    = (float*)d_out;

    hist_kernel<<<NFRAMES, 256>>>(frames);

    cudaFuncSetAttribute(band_kernel,
                         cudaFuncAttributeMaxDynamicSharedMemorySize, BAND_SMEM);
    band_kernel<<<dim3(TLEN / TT, BATCH), 256, BAND_SMEM>>>();

    cudaFuncSetAttribute(gemv_kernel,
                         cudaFuncAttributeMaxDynamicSharedMemorySize, GEMV_SMEM);
    gemv_kernel<<<NFRAMES / GT, 256, GEMV_SMEM>>>(fc_w, fc_b, out);
}

// round 6
// speedup vs baseline: 1.0005x; 1.0005x over previous
#include <cuda_runtime.h>
#include <cuda_bf16.h>

// Problem constants
#define BATCH   4
#define TLEN    1024
#define PIX     1296          // 27*48
#define NBINS   512
#define LOOKUP  101
#define PAD     50
#define OUTDIM  128
#define NFRAMES (BATCH * TLEN)    // 4096

// Band kernel tiling
#define TT      8                  // t-rows per CTA
#define RR      (TT + 2 * PAD)     // 108 staged rows
#define BAND_SMEM (RR * NBINS * 4) // 221184 bytes

// GEMV tiling
#define GT      16                 // (b,t) rows per CTA
#define GEMV_SMEM ((LOOKUP * OUTDIM + GT * LOOKUP) * 4) // 58176 bytes

// Scratch (static device globals: no allocation allowed)
__device__ float g_hist[NFRAMES * NBINS];   // 8 MB, L2-normalized histograms
__device__ float g_win[NFRAMES * LOOKUP];   // 1.65 MB, banded similarities

// ---------------------------------------------------------------------------
// Kernel 1: per-frame 512-bin color histogram + L2 normalize.
// One CTA per frame. HBM-bound on the 64MB int32 input.
// ---------------------------------------------------------------------------
__global__ void __launch_bounds__(256) hist_kernel(const int* __restrict__ frames) {
    __shared__ int h[NBINS];
    __shared__ float red[9];

    const int f = blockIdx.x;
    const int tid = threadIdx.x;

    for (int i = tid; i < NBINS; i += 256) h[i] = 0;
    __syncthreads();

    const int* fp = frames + (long long)f * (PIX * 3);
    for (int p = tid; p < PIX; p += 256) {
        int r = fp[3 * p + 0];
        int g = fp[3 * p + 1];
        int b = fp[3 * p + 2];
        int bin = ((r >> 5) << 6) | ((g >> 5) << 3) | (b >> 5);
        atomicAdd(&h[bin], 1);
    }
    __syncthreads();

    // sum of squares -> 1/norm
    float s = 0.0f;
    for (int i = tid; i < NBINS; i += 256) {
        float v = (float)h[i];
        s = fmaf(v, v, s);
    }
    #pragma unroll
    for (int off = 16; off; off >>= 1) s += __shfl_xor_sync(0xffffffffu, s, off);
    if ((tid & 31) == 0) red[tid >> 5] = s;
    __syncthreads();
    if (tid == 0) {
        float tot = 0.0f;
        #pragma unroll
        for (int i = 0; i < 8; i++) tot += red[i];
        red[8] = 1.0f / sqrtf(fmaxf(tot, 1e-24f));
    }
    __syncthreads();
    const float inv = red[8];

    float* dst = g_hist + (long long)f * NBINS;
    for (int i = tid; i < NBINS; i += 256)
        dst[i] = (float)h[i] * inv;
}

// ---------------------------------------------------------------------------
// Kernel 2: banded similarities.
//   win[b, t, l] = dot(x[b,t], x[b, t+l-50]) over 512 dims (0 if out of range)
// CTA handles TT=8 consecutive t of one batch. Stages the 108 needed rows in
// SMEM (216KB), keeps the 8 query rows in registers (128 regs/thread), so each
// staged row chunk is LDS-read once per warp and FMA'd against 8 queries.
// ---------------------------------------------------------------------------
__device__ __forceinline__ float dot4(float4 a, float4 b, float s) {
    s = fmaf(a.x, b.x, s);
    s = fmaf(a.y, b.y, s);
    s = fmaf(a.z, b.z, s);
    s = fmaf(a.w, b.w, s);
    return s;
}

__global__ void __launch_bounds__(256, 1) band_kernel() {
    extern __shared__ float rows[];            // RR * NBINS floats
    float4* rows4 = reinterpret_cast<float4*>(rows);

    const int t0  = blockIdx.x * TT;
    const int b   = blockIdx.y;
    const int tid = threadIdx.x;

    // Stage rows [t0-50, t0+57] (zero-fill out-of-range) into SMEM.
    const float4* gh4 = reinterpret_cast<const float4*>(g_hist);
    for (int idx = tid; idx < RR * (NBINS / 4); idx += 256) {
        int r = idx >> 7;          // NBINS/4 = 128 float4 per row
        int c = idx & 127;
        int j = t0 - PAD + r;
        float4 v = make_float4(0.f, 0.f, 0.f, 0.f);
        if (j >= 0 && j < TLEN)
            v = gh4[(b * TLEN + j) * (NBINS / 4) + c];
        rows4[idx] = v;
    }
    __syncthreads();

    const int w    = tid >> 5;
    const int lane = tid & 31;

    // Query rows (t0..t0+7) in registers: each lane owns k-chunks
    // {lane, lane+32, lane+64, lane+96} (float4 granularity).
    float4 xa[TT][4];
    #pragma unroll
    for (int ti = 0; ti < TT; ti++) {
        #pragma unroll
        for (int i = 0; i < 4; i++)
            xa[ti][i] = rows4[(PAD + ti) * 128 + lane + 32 * i];
    }

    // Each warp sweeps its subset of staged rows r (= key row j = t0-50+r).
    for (int r = w; r < RR; r += 8) {
        float4 xb0 = rows4[r * 128 + lane];
        float4 xb1 = rows4[r * 128 + lane + 32];
        float4 xb2 = rows4[r * 128 + lane + 64];
        float4 xb3 = rows4[r * 128 + lane + 96];

        float acc[TT];
        #pragma unroll
        for (int ti = 0; ti < TT; ti++) {
            float s = 0.0f;
            s = dot4(xa[ti][0], xb0, s);
            s = dot4(xa[ti][1], xb1, s);
            s = dot4(xa[ti][2], xb2, s);
            s = dot4(xa[ti][3], xb3, s);
            acc[ti] = s;
        }

        #pragma unroll
        for (int ti = 0; ti < TT; ti++) {
            float v = acc[ti];
            #pragma unroll
            for (int off = 16; off; off >>= 1)
                v += __shfl_xor_sync(0xffffffffu, v, off);
            int l = r - ti;                      // l = j - t + 50
            if (lane == ti && l >= 0 && l < LOOKUP)
                g_win[(b * TLEN + t0 + ti) * LOOKUP + l] = v;
        }
    }
}

// ---------------------------------------------------------------------------
// Kernel 3: out[bt, o] = relu( sum_l win[bt, l] * W[l, o] + bias[o] )
// CTA handles GT=16 (b,t) rows; fc_w staged in SMEM once per CTA.
// ---------------------------------------------------------------------------
__global__ void __launch_bounds__(256) gemv_kernel(const float* __restrict__ W,
                                                   const float* __restrict__ bias,
                                                   float* __restrict__ out) {
    extern __shared__ float sm[];
    float* Wsh   = sm;                       // LOOKUP*OUTDIM
    float* winsh = sm + LOOKUP * OUTDIM;     // GT*LOOKUP

    const int tid = threadIdx.x;
    const int f0  = blockIdx.x * GT;

    const float4* W4   = reinterpret_cast<const float4*>(W);
    float4*       Wsh4 = reinterpret_cast<float4*>(Wsh);
    for (int i = tid; i < LOOKUP * (OUTDIM / 4); i += 256) Wsh4[i] = W4[i];
    for (int i = tid; i < GT * LOOKUP; i += 256) winsh[i] = g_win[f0 * LOOKUP + i];
    __syncthreads();

    const int o    = tid & 127;
    const int half = tid >> 7;               // 0 or 1

    float acc[GT / 2];
    const float bo = bias[o];
    #pragma unroll
    for (int i = 0; i < GT / 2; i++) acc[i] = bo;

    for (int l = 0; l < LOOKUP; l++) {
        float wv = Wsh[l * OUTDIM + o];
        #pragma unroll
        for (int i = 0; i < GT / 2; i++)
            acc[i] = fmaf(winsh[(half + 2 * i) * LOOKUP + l], wv, acc[i]);
    }

    #pragma unroll
    for (int i = 0; i < GT / 2; i++)
        out[(f0 + half + 2 * i) * OUTDIM + o] = fmaxf(acc[i], 0.0f);
}

// ---------------------------------------------------------------------------
extern "C" void kernel_launch(void* const* d_in, const int* in_sizes, int n_in,
                              void* d_out, int out_size) {
    const int*   frames = (const int*)d_in[0];
    const float* fc_w   = (const float*)d_in[1];
    const float* fc_b   = (const float*)d_in[2];
    float*       out    = (float*)d_out;

    hist_kernel<<<NFRAMES, 256>>>(frames);

    cudaFuncSetAttribute(band_kernel,
                         cudaFuncAttributeMaxDynamicSharedMemorySize, BAND_SMEM);
    band_kernel<<<dim3(TLEN / TT, BATCH), 256, BAND_SMEM>>>();

    cudaFuncSetAttribute(gemv_kernel,
                         cudaFuncAttributeMaxDynamicSharedMemorySize, GEMV_SMEM);
    gemv_kernel<<<NFRAMES / GT, 256, GEMV_SMEM>>>(fc_w, fc_b, out);
}

// round 7
// speedup vs baseline: 1.0235x; 1.0230x over previous
#include <cuda_runtime.h>
#include <cuda_bf16.h>

// Problem constants
#define BATCH   4
#define TLEN    1024
#define PIX     1296          // 27*48
#define NBINS   512
#define LOOKUP  101
#define PAD     50
#define OUTDIM  128
#define NFRAMES (BATCH * TLEN)    // 4096

// Band kernel tiling
#define TT      8                  // t-rows per CTA
#define RR      (TT + 2 * PAD)     // 108 staged rows
#define BAND_SMEM (RR * NBINS * 4) // 221184 bytes

// GEMV tiling
#define GT      16                 // (b,t) rows per CTA
#define GEMV_SMEM ((LOOKUP * OUTDIM + GT * LOOKUP) * 4) // 58176 bytes

// Scratch (static device globals: no allocation allowed)
__device__ float g_hist[NFRAMES * NBINS];   // 8 MB, L2-normalized histograms
__device__ float g_win[NFRAMES * LOOKUP];   // 1.65 MB, banded similarities

// ---------------------------------------------------------------------------
// Kernel 1: per-frame 512-bin color histogram + L2 normalize.
// One CTA per frame. HBM-bound on the 64MB int32 input.
// ---------------------------------------------------------------------------
__global__ void __launch_bounds__(256) hist_kernel(const int* __restrict__ frames) {
    __shared__ int h[NBINS];
    __shared__ float red[9];

    const int f = blockIdx.x;
    const int tid = threadIdx.x;

    for (int i = tid; i < NBINS; i += 256) h[i] = 0;
    __syncthreads();

    const int* fp = frames + (long long)f * (PIX * 3);
    for (int p = tid; p < PIX; p += 256) {
        int r = fp[3 * p + 0];
        int g = fp[3 * p + 1];
        int b = fp[3 * p + 2];
        int bin = ((r >> 5) << 6) | ((g >> 5) << 3) | (b >> 5);
        atomicAdd(&h[bin], 1);
    }
    __syncthreads();

    // sum of squares -> 1/norm
    float s = 0.0f;
    for (int i = tid; i < NBINS; i += 256) {
        float v = (float)h[i];
        s = fmaf(v, v, s);
    }
    #pragma unroll
    for (int off = 16; off; off >>= 1) s += __shfl_xor_sync(0xffffffffu, s, off);
    if ((tid & 31) == 0) red[tid >> 5] = s;
    __syncthreads();
    if (tid == 0) {
        float tot = 0.0f;
        #pragma unroll
        for (int i = 0; i < 8; i++) tot += red[i];
        red[8] = 1.0f / sqrtf(fmaxf(tot, 1e-24f));
    }
    __syncthreads();
    const float inv = red[8];

    float* dst = g_hist + (long long)f * NBINS;
    for (int i = tid; i < NBINS; i += 256)
        dst[i] = (float)h[i] * inv;
}

// ---------------------------------------------------------------------------
// Kernel 2: banded similarities.
//   win[b, t, l] = dot(x[b,t], x[b, t+l-50]) over 512 dims (0 if out of range)
// CTA handles TT=8 consecutive t of one batch. Stages the 108 needed rows in
// SMEM (216KB), keeps the 8 query rows in registers (128 regs/thread), so each
// staged row chunk is LDS-read once per warp and FMA'd against 8 queries.
// ---------------------------------------------------------------------------
__device__ __forceinline__ float dot4(float4 a, float4 b, float s) {
    s = fmaf(a.x, b.x, s);
    s = fmaf(a.y, b.y, s);
    s = fmaf(a.z, b.z, s);
    s = fmaf(a.w, b.w, s);
    return s;
}

__global__ void __launch_bounds__(256, 1) band_kernel() {
    extern __shared__ float rows[];            // RR * NBINS floats
    float4* rows4 = reinterpret_cast<float4*>(rows);

    const int t0  = blockIdx.x * TT;
    const int b   = blockIdx.y;
    const int tid = threadIdx.x;

    // Stage rows [t0-50, t0+57] (zero-fill out-of-range) into SMEM.
    const float4* gh4 = reinterpret_cast<const float4*>(g_hist);
    for (int idx = tid; idx < RR * (NBINS / 4); idx += 256) {
        int r = idx >> 7;          // NBINS/4 = 128 float4 per row
        int c = idx & 127;
        int j = t0 - PAD + r;
        float4 v = make_float4(0.f, 0.f, 0.f, 0.f);
        if (j >= 0 && j < TLEN)
            v = gh4[(b * TLEN + j) * (NBINS / 4) + c];
        rows4[idx] = v;
    }
    __syncthreads();

    const int w    = tid >> 5;
    const int lane = tid & 31;

    // Query rows (t0..t0+7) in registers: each lane owns k-chunks
    // {lane, lane+32, lane+64, lane+96} (float4 granularity).
    float4 xa[TT][4];
    #pragma unroll
    for (int ti = 0; ti < TT; ti++) {
        #pragma unroll
        for (int i = 0; i < 4; i++)
            xa[ti][i] = rows4[(PAD + ti) * 128 + lane + 32 * i];
    }

    // Each warp sweeps its subset of staged rows r (= key row j = t0-50+r).
    for (int r = w; r < RR; r += 8) {
        float4 xb0 = rows4[r * 128 + lane];
        float4 xb1 = rows4[r * 128 + lane + 32];
        float4 xb2 = rows4[r * 128 + lane + 64];
        float4 xb3 = rows4[r * 128 + lane + 96];

        float acc[TT];
        #pragma unroll
        for (int ti = 0; ti < TT; ti++) {
            float s = 0.0f;
            s = dot4(xa[ti][0], xb0, s);
            s = dot4(xa[ti][1], xb1, s);
            s = dot4(xa[ti][2], xb2, s);
            s = dot4(xa[ti][3], xb3, s);
            acc[ti] = s;
        }

        #pragma unroll
        for (int ti = 0; ti < TT; ti++) {
            float v = acc[ti];
            #pragma unroll
            for (int off = 16; off; off >>= 1)
                v += __shfl_xor_sync(0xffffffffu, v, off);
            int l = r - ti;                      // l = j - t + 50
            if (lane == ti && l >= 0 && l < LOOKUP)
                g_win[(b * TLEN + t0 + ti) * LOOKUP + l] = v;
        }
    }
}

// ---------------------------------------------------------------------------
// Kernel 3: out[bt, o] = relu( sum_l win[bt, l] * W[l, o] + bias[o] )
// CTA handles GT=16 (b,t) rows; fc_w staged in SMEM once per CTA.
// ---------------------------------------------------------------------------
__global__ void __launch_bounds__(256) gemv_kernel(const float* __restrict__ W,
                                                   const float* __restrict__ bias,
                                                   float* __restrict__ out) {
    extern __shared__ float sm[];
    float* Wsh   = sm;                       // LOOKUP*OUTDIM
    float* winsh = sm + LOOKUP * OUTDIM;     // GT*LOOKUP

    const int tid = threadIdx.x;
    const int f0  = blockIdx.x * GT;

    const float4* W4   = reinterpret_cast<const float4*>(W);
    float4*       Wsh4 = reinterpret_cast<float4*>(Wsh);
    for (int i = tid; i < LOOKUP * (OUTDIM / 4); i += 256) Wsh4[i] = W4[i];
    for (int i = tid; i < GT * LOOKUP; i += 256) winsh[i] = g_win[f0 * LOOKUP + i];
    __syncthreads();

    const int o    = tid & 127;
    const int half = tid >> 7;               // 0 or 1

    float acc[GT / 2];
    const float bo = bias[o];
    #pragma unroll
    for (int i = 0; i < GT / 2; i++) acc[i] = bo;

    for (int l = 0; l < LOOKUP; l++) {
        float wv = Wsh[l * OUTDIM + o];
        #pragma unroll
        for (int i = 0; i < GT / 2; i++)
            acc[i] = fmaf(winsh[(half + 2 * i) * LOOKUP + l], wv, acc[i]);
    }

    #pragma unroll
    for (int i = 0; i < GT / 2; i++)
        out[(f0 + half + 2 * i) * OUTDIM + o] = fmaxf(acc[i], 0.0f);
}

// ---------------------------------------------------------------------------
extern "C" void kernel_launch(void* const* d_in, const int* in_sizes, int n_in,
                              void* d_out, int out_size) {
    const int*   frames = (const int*)d_in[0];
    const float* fc_w   = (const float*)d_in[1];
    const float* fc_b   = (const float*)d_in[2];
    float*       out    = (float*)d_out;

    hist_kernel<<<NFRAMES, 256>>>(frames);

    cudaFuncSetAttribute(band_kernel,
                         cudaFuncAttributeMaxDynamicSharedMemorySize, BAND_SMEM);
    band_kernel<<<dim3(TLEN / TT, BATCH), 256, BAND_SMEM>>>();

    cudaFuncSetAttribute(gemv_kernel,
                         cudaFuncAttributeMaxDynamicSharedMemorySize, GEMV_SMEM);
    gemv_kernel<<<NFRAMES / GT, 256, GEMV_SMEM>>>(fc_w, fc_b, out);
}

// round 8
// speedup vs baseline: 1.0240x; 1.0005x over previous
#include <cuda_runtime.h>
#include <cuda_bf16.h>

// Problem constants
#define BATCH   4
#define TLEN    1024
#define PIX     1296          // 27*48
#define NBINS   512
#define LOOKUP  101
#define PAD     50
#define OUTDIM  128
#define NFRAMES (BATCH * TLEN)    // 4096

// Band kernel tiling
#define TT      8                  // t-rows per CTA
#define RR      (TT + 2 * PAD)     // 108 staged rows
#define BAND_SMEM (RR * NBINS * 4) // 221184 bytes

// GEMV tiling
#define GT      16                 // (b,t) rows per CTA
#define GEMV_SMEM ((LOOKUP * OUTDIM + GT * LOOKUP) * 4) // 58176 bytes

// Scratch (static device globals: no allocation allowed)
__device__ float g_hist[NFRAMES * NBINS];   // 8 MB, L2-normalized histograms
__device__ float g_win[NFRAMES * LOOKUP];   // 1.65 MB, banded similarities

// ---------------------------------------------------------------------------
// Kernel 1: per-frame 512-bin color histogram + L2 normalize.
// One CTA per frame. HBM-bound on the 64MB int32 input.
// ---------------------------------------------------------------------------
__global__ void __launch_bounds__(256) hist_kernel(const int* __restrict__ frames) {
    __shared__ int h[NBINS];
    __shared__ float red[9];

    const int f = blockIdx.x;
    const int tid = threadIdx.x;

    for (int i = tid; i < NBINS; i += 256) h[i] = 0;
    __syncthreads();

    const int* fp = frames + (long long)f * (PIX * 3);
    for (int p = tid; p < PIX; p += 256) {
        int r = fp[3 * p + 0];
        int g = fp[3 * p + 1];
        int b = fp[3 * p + 2];
        int bin = ((r >> 5) << 6) | ((g >> 5) << 3) | (b >> 5);
        atomicAdd(&h[bin], 1);
    }
    __syncthreads();

    // sum of squares -> 1/norm
    float s = 0.0f;
    for (int i = tid; i < NBINS; i += 256) {
        float v = (float)h[i];
        s = fmaf(v, v, s);
    }
    #pragma unroll
    for (int off = 16; off; off >>= 1) s += __shfl_xor_sync(0xffffffffu, s, off);
    if ((tid & 31) == 0) red[tid >> 5] = s;
    __syncthreads();
    if (tid == 0) {
        float tot = 0.0f;
        #pragma unroll
        for (int i = 0; i < 8; i++) tot += red[i];
        red[8] = 1.0f / sqrtf(fmaxf(tot, 1e-24f));
    }
    __syncthreads();
    const float inv = red[8];

    float* dst = g_hist + (long long)f * NBINS;
    for (int i = tid; i < NBINS; i += 256)
        dst[i] = (float)h[i] * inv;
}

// ---------------------------------------------------------------------------
// Kernel 2: banded similarities.
//   win[b, t, l] = dot(x[b,t], x[b, t+l-50]) over 512 dims (0 if out of range)
// CTA handles TT=8 consecutive t of one batch. Stages the 108 needed rows in
// SMEM (216KB), keeps the 8 query rows in registers (128 regs/thread), so each
// staged row chunk is LDS-read once per warp and FMA'd against 8 queries.
// ---------------------------------------------------------------------------
__device__ __forceinline__ float dot4(float4 a, float4 b, float s) {
    s = fmaf(a.x, b.x, s);
    s = fmaf(a.y, b.y, s);
    s = fmaf(a.z, b.z, s);
    s = fmaf(a.w, b.w, s);
    return s;
}

__global__ void __launch_bounds__(256, 1) band_kernel() {
    extern __shared__ float rows[];            // RR * NBINS floats
    float4* rows4 = reinterpret_cast<float4*>(rows);

    const int t0  = blockIdx.x * TT;
    const int b   = blockIdx.y;
    const int tid = threadIdx.x;

    // Stage rows [t0-50, t0+57] (zero-fill out-of-range) into SMEM.
    const float4* gh4 = reinterpret_cast<const float4*>(g_hist);
    for (int idx = tid; idx < RR * (NBINS / 4); idx += 256) {
        int r = idx >> 7;          // NBINS/4 = 128 float4 per row
        int c = idx & 127;
        int j = t0 - PAD + r;
        float4 v = make_float4(0.f, 0.f, 0.f, 0.f);
        if (j >= 0 && j < TLEN)
            v = gh4[(b * TLEN + j) * (NBINS / 4) + c];
        rows4[idx] = v;
    }
    __syncthreads();

    const int w    = tid >> 5;
    const int lane = tid & 31;

    // Query rows (t0..t0+7) in registers: each lane owns k-chunks
    // {lane, lane+32, lane+64, lane+96} (float4 granularity).
    float4 xa[TT][4];
    #pragma unroll
    for (int ti = 0; ti < TT; ti++) {
        #pragma unroll
        for (int i = 0; i < 4; i++)
            xa[ti][i] = rows4[(PAD + ti) * 128 + lane + 32 * i];
    }

    // Each warp sweeps its subset of staged rows r (= key row j = t0-50+r).
    for (int r = w; r < RR; r += 8) {
        float4 xb0 = rows4[r * 128 + lane];
        float4 xb1 = rows4[r * 128 + lane + 32];
        float4 xb2 = rows4[r * 128 + lane + 64];
        float4 xb3 = rows4[r * 128 + lane + 96];

        float acc[TT];
        #pragma unroll
        for (int ti = 0; ti < TT; ti++) {
            float s = 0.0f;
            s = dot4(xa[ti][0], xb0, s);
            s = dot4(xa[ti][1], xb1, s);
            s = dot4(xa[ti][2], xb2, s);
            s = dot4(xa[ti][3], xb3, s);
            acc[ti] = s;
        }

        #pragma unroll
        for (int ti = 0; ti < TT; ti++) {
            float v = acc[ti];
            #pragma unroll
            for (int off = 16; off; off >>= 1)
                v += __shfl_xor_sync(0xffffffffu, v, off);
            int l = r - ti;                      // l = j - t + 50
            if (lane == ti && l >= 0 && l < LOOKUP)
                g_win[(b * TLEN + t0 + ti) * LOOKUP + l] = v;
        }
    }
}

// ---------------------------------------------------------------------------
// Kernel 3: out[bt, o] = relu( sum_l win[bt, l] * W[l, o] + bias[o] )
// CTA handles GT=16 (b,t) rows; fc_w staged in SMEM once per CTA.
// ---------------------------------------------------------------------------
__global__ void __launch_bounds__(256) gemv_kernel(const float* __restrict__ W,
                                                   const float* __restrict__ bias,
                                                   float* __restrict__ out) {
    extern __shared__ float sm[];
    float* Wsh   = sm;                       // LOOKUP*OUTDIM
    float* winsh = sm + LOOKUP * OUTDIM;     // GT*LOOKUP

    const int tid = threadIdx.x;
    const int f0  = blockIdx.x * GT;

    const float4* W4   = reinterpret_cast<const float4*>(W);
    float4*       Wsh4 = reinterpret_cast<float4*>(Wsh);
    for (int i = tid; i < LOOKUP * (OUTDIM / 4); i += 256) Wsh4[i] = W4[i];
    for (int i = tid; i < GT * LOOKUP; i += 256) winsh[i] = g_win[f0 * LOOKUP + i];
    __syncthreads();

    const int o    = tid & 127;
    const int half = tid >> 7;               // 0 or 1

    float acc[GT / 2];
    const float bo = bias[o];
    #pragma unroll
    for (int i = 0; i < GT / 2; i++) acc[i] = bo;

    for (int l = 0; l < LOOKUP; l++) {
        float wv = Wsh[l * OUTDIM + o];
        #pragma unroll
        for (int i = 0; i < GT / 2; i++)
            acc[i] = fmaf(winsh[(half + 2 * i) * LOOKUP + l], wv, acc[i]);
    }

    #pragma unroll
    for (int i = 0; i < GT / 2; i++)
        out[(f0 + half + 2 * i) * OUTDIM + o] = fmaxf(acc[i], 0.0f);
}

// ---------------------------------------------------------------------------
extern "C" void kernel_launch(void* const* d_in, const int* in_sizes, int n_in,
                              void* d_out, int out_size) {
    const int*   frames = (const int*)d_in[0];
    const float* fc_w   = (const float*)d_in[1];
    const float* fc_b   = (const float*)d_in[2];
    float*       out    = (float*)d_out;

    hist_kernel<<<NFRAMES, 256>>>(frames);

    cudaFuncSetAttribute(band_kernel,
                         cudaFuncAttributeMaxDynamicSharedMemorySize, BAND_SMEM);
    band_kernel<<<dim3(TLEN / TT, BATCH), 256, BAND_SMEM>>>();

    cudaFuncSetAttribute(gemv_kernel,
                         cudaFuncAttributeMaxDynamicSharedMemorySize, GEMV_SMEM);
    gemv_kernel<<<NFRAMES / GT, 256, GEMV_SMEM>>>(fc_w, fc_b, out);
}